// round 3
// baseline (speedup 1.0000x reference)
#include <cuda_runtime.h>

// LossGenerator: T=11, H=W=2048. Inputs u=output, f1, each [11,1,2048,2048] f32.
// Output: [phy, bc] f32. Single fused kernel; warp-shuffle halo exchange
// (lane-contiguous w mapping) to cut L1tex wavefront traffic ~2x.

#define HH 2048
#define WI 2048
static const size_t HWs = (size_t)HH * (size_t)WI;

#define NB_BC   10
#define NB_PHY  4096     // 16 w-segments x 256 row-groups (8 rows each)
#define NB_TOT  (NB_BC + NB_PHY)

__device__ double   g_phy;
__device__ double   g_bc;
__device__ unsigned g_count;

constexpr double PREFD = 3.5682482323055424;  // 0.1^{-0.5}/Gamma(1.5)
constexpr double WQ[10] = {
    1.0,
    0.41421356237309515,
    0.31783724519578215,
    0.26794919243112270,
    0.23606797749978969,
    0.21342176528338802,
    0.19626156828141264,
    0.18267581368159972,
    0.17157287525380971,
    0.16227766016837933
};

__device__ __forceinline__ void block_reduce_add(double v, double* target, int tid) {
    #pragma unroll
    for (int o = 16; o > 0; o >>= 1)
        v += __shfl_down_sync(0xffffffffu, v, o);
    __shared__ double sr[8];
    int lane = tid & 31, wid = tid >> 5;
    if (lane == 0) sr[wid] = v;
    __syncthreads();
    if (wid == 0) {
        v = (lane < 8) ? sr[lane] : 0.0;
        #pragma unroll
        for (int o = 4; o > 0; o >>= 1)
            v += __shfl_down_sync(0xffffffffu, v, o);
        if (lane == 0) atomicAdd(target, v);
    }
}

__global__ __launch_bounds__(256) void fused_kernel(const float* __restrict__ u,
                                                    const float* __restrict__ f1,
                                                    float* __restrict__ out) {
    const int tid = threadIdx.x;
    const int bid = blockIdx.x;

    if (bid < NB_BC) {
        // ---------------- boundary-condition loss ----------------
        const int it = bid;                      // time slice it+1
        const float* ut = u + (size_t)(it + 1) * HWs;
        const float tval = 0.1f + 0.1f * (float)it;
        const float tt = powf(tval, 1.5f);

        double v = 0.0;
        #pragma unroll
        for (int jb = 0; jb < 8; jb++) {
            const int j = jb * 256 + tid;        // 0..2047
            const float xj = (float)j * (1.0f / 2047.0f);
            const float x1b = tt * sinf(6.2831853071795862f * xj);

            const float l  = ut[(size_t)j * WI];
            const float r  = ut[(size_t)j * WI + (WI - 1)];
            const float tp = ut[j];
            const float bt = ut[(size_t)(HH - 1) * WI + j];

            const float dl = l - x1b, dr = r - x1b, du = tp - x1b, db = bt - x1b;
            v += (double)(dl * dl + dr * dr + du * du + db * db);
        }
        block_reduce_add(v, &g_bc, tid);
    } else {
        // ---------------- physics residual loss ----------------
        const int b    = bid - NB_BC;
        const int lane = tid & 31;
        const int wrp  = tid >> 5;               // 0..7
        const int seg  = b & 15;                 // w segment of 128 px
        const int h    = 1 + (b >> 4) * 8 + wrp; // row, 1..2048 (mask > 2046)
        const int w0   = seg * 128 + lane * 4;   // 0..2044, 16B aligned

        float acc = 0.0f;

        if (h <= HH - 2) {
            const float A = 0.34520446044393f;
            const float B = 0.309591078922457f;
            const float C = -2.619182157203629f;
            const float KLAP = 0.01f * 4194304.0f;     // kappa / DX^2

            const float fPW[10] = {
                (float)(PREFD * WQ[0]), (float)(PREFD * WQ[1]), (float)(PREFD * WQ[2]),
                (float)(PREFD * WQ[3]), (float)(PREFD * WQ[4]), (float)(PREFD * WQ[5]),
                (float)(PREFD * WQ[6]), (float)(PREFD * WQ[7]), (float)(PREFD * WQ[8]),
                (float)(PREFD * WQ[9])
            };
            const float fPD[10] = {
                0.0f,
                (float)(PREFD * (WQ[0] - WQ[1])), (float)(PREFD * (WQ[1] - WQ[2])),
                (float)(PREFD * (WQ[2] - WQ[3])), (float)(PREFD * (WQ[3] - WQ[4])),
                (float)(PREFD * (WQ[4] - WQ[5])), (float)(PREFD * (WQ[5] - WQ[6])),
                (float)(PREFD * (WQ[6] - WQ[7])), (float)(PREFD * (WQ[7] - WQ[8])),
                (float)(PREFD * (WQ[8] - WQ[9]))
            };
            const float PREFF = (float)PREFD;

            const float msk0 = (w0 == 0)      ? 0.0f : 1.0f;
            const float msk3 = (w0 == WI - 4) ? 0.0f : 1.0f;
            const bool loadL = (lane == 0)  && (w0 > 0);
            const bool loadR = (lane == 31) && (w0 < WI - 4);

            float uc[11][4];
            const size_t base = (size_t)(h - 1) * WI + (size_t)w0;

            #pragma unroll
            for (int t = 0; t < 11; t++) {
                const float* pt = u + (size_t)t * HWs + base;   // row h-1
                const float* pm = pt + WI;                       // row h
                const float* pb = pm + WI;                       // row h+1
                const float4 a4 = *(const float4*)pt;
                const float4 m4 = *(const float4*)pm;
                const float4 b4 = *(const float4*)pb;
                const float4 f4 = __ldcs((const float4*)(f1 + (size_t)t * HWs + base + WI));

                float elT = 0.f, elM = 0.f, elB = 0.f;
                float erT = 0.f, erM = 0.f, erB = 0.f;
                if (loadL) { elT = pt[-1]; elM = pm[-1]; elB = pb[-1]; }
                if (loadR) { erT = pt[4];  erM = pm[4];  erB = pb[4]; }

                float slT = __shfl_up_sync(0xffffffffu, a4.w, 1);
                float slM = __shfl_up_sync(0xffffffffu, m4.w, 1);
                float slB = __shfl_up_sync(0xffffffffu, b4.w, 1);
                float srT = __shfl_down_sync(0xffffffffu, a4.x, 1);
                float srM = __shfl_down_sync(0xffffffffu, m4.x, 1);
                float srB = __shfl_down_sync(0xffffffffu, b4.x, 1);
                if (lane == 0)  { slT = elT; slM = elM; slB = elB; }
                if (lane == 31) { srT = erT; srM = erM; srB = erB; }

                const float tc[6] = { slT, a4.x, a4.y, a4.z, a4.w, srT };
                const float mc[6] = { slM, m4.x, m4.y, m4.z, m4.w, srM };
                const float bb[6] = { slB, b4.x, b4.y, b4.z, b4.w, srB };
                const float ff[4] = { f4.x, f4.y, f4.z, f4.w };
                const float msk[4] = { msk0, 1.0f, 1.0f, msk3 };

                #pragma unroll
                for (int j = 0; j < 4; j++) {
                    const float center = mc[j + 1];
                    float conv = A * (tc[j] + tc[j + 2] + bb[j] + bb[j + 2])
                               + B * (tc[j + 1] + bb[j + 1] + mc[j] + mc[j + 2])
                               + C * center;
                    float fu = center - ff[j] - KLAP * conv;
                    if (t > 0) {
                        float Dv = PREFF * center - fPW[t - 1] * uc[0][j];
                        #pragma unroll
                        for (int k = 1; k < t; k++)
                            Dv -= fPD[t - k] * uc[k][j];
                        fu += Dv;
                    }
                    fu *= msk[j];
                    acc += fu * fu;
                    uc[t][j] = center;
                }
            }
        }

        block_reduce_add((double)acc, &g_phy, tid);
    }

    // ---------------- last-block finalize + reset ----------------
    if (tid == 0) {
        __threadfence();
        unsigned prev = atomicAdd(&g_count, 1u);
        if (prev == NB_TOT - 1) {
            out[0] = (float)(2.0 * g_phy / 46047276.0);   // 11*2046*2046
            out[1] = (float)(g_bc / 41943040.0);          // 10*2048*2048
            g_phy = 0.0;
            g_bc  = 0.0;
            g_count = 0u;
            __threadfence();
        }
    }
}

extern "C" void kernel_launch(void* const* d_in, const int* in_sizes, int n_in,
                              void* d_out, int out_size) {
    const float* u  = (const float*)d_in[0];
    const float* f1 = (const float*)d_in[1];
    float* out = (float*)d_out;

    fused_kernel<<<NB_TOT, 256>>>(u, f1, out);
}

// round 4
// speedup vs baseline: 1.2316x; 1.2316x over previous
#include <cuda_runtime.h>

// LossGenerator: T=11, H=W=2048. Inputs u=output, f1, each [11,1,2048,2048] f32.
// Output: [phy, bc] f32. Single fused kernel.
// Stencil separated as q = A*(top+bot) + B*mid; conv = q[j-1]+q[j+1]+B*colA+C*mid
// -> only 2 warp shuffles per time slice for the horizontal halo.

#define HH 2048
#define WI 2048
static const size_t HWs = (size_t)HH * (size_t)WI;

#define NB_BC   10
#define NB_PHY  4096     // 16 w-segments x 256 row-groups (8 rows each)
#define NB_TOT  (NB_BC + NB_PHY)

__device__ double   g_phy;
__device__ double   g_bc;
__device__ unsigned g_count;

constexpr double PREFD = 3.5682482323055424;  // 0.1^{-0.5}/Gamma(1.5)
constexpr double WQ[10] = {
    1.0,
    0.41421356237309515,
    0.31783724519578215,
    0.26794919243112270,
    0.23606797749978969,
    0.21342176528338802,
    0.19626156828141264,
    0.18267581368159972,
    0.17157287525380971,
    0.16227766016837933
};

__device__ __forceinline__ void block_reduce_add(double v, double* target, int tid) {
    #pragma unroll
    for (int o = 16; o > 0; o >>= 1)
        v += __shfl_down_sync(0xffffffffu, v, o);
    __shared__ double sr[8];
    int lane = tid & 31, wid = tid >> 5;
    if (lane == 0) sr[wid] = v;
    __syncthreads();
    if (wid == 0) {
        v = (lane < 8) ? sr[lane] : 0.0;
        #pragma unroll
        for (int o = 4; o > 0; o >>= 1)
            v += __shfl_down_sync(0xffffffffu, v, o);
        if (lane == 0) atomicAdd(target, v);
    }
}

__global__ __launch_bounds__(256) void fused_kernel(const float* __restrict__ u,
                                                    const float* __restrict__ f1,
                                                    float* __restrict__ out) {
    const int tid = threadIdx.x;
    const int bid = blockIdx.x;

    if (bid < NB_BC) {
        // ---------------- boundary-condition loss ----------------
        const int it = bid;                      // time slice it+1
        const float* ut = u + (size_t)(it + 1) * HWs;
        const float tval = 0.1f + 0.1f * (float)it;
        const float tt = powf(tval, 1.5f);

        double v = 0.0;
        #pragma unroll
        for (int jb = 0; jb < 8; jb++) {
            const int j = jb * 256 + tid;        // 0..2047
            const float xj = (float)j * (1.0f / 2047.0f);
            const float x1b = tt * sinf(6.2831853071795862f * xj);

            const float l  = ut[(size_t)j * WI];
            const float r  = ut[(size_t)j * WI + (WI - 1)];
            const float tp = ut[j];
            const float bt = ut[(size_t)(HH - 1) * WI + j];

            const float dl = l - x1b, dr = r - x1b, du = tp - x1b, db = bt - x1b;
            v += (double)(dl * dl + dr * dr + du * du + db * db);
        }
        block_reduce_add(v, &g_bc, tid);
    } else {
        // ---------------- physics residual loss ----------------
        const int b    = bid - NB_BC;
        const int lane = tid & 31;
        const int wrp  = tid >> 5;               // 0..7
        const int seg  = b & 15;                 // w segment of 128 px
        const int h    = 1 + (b >> 4) * 8 + wrp; // row, 1..2048 (mask > 2046)
        const int w0   = seg * 128 + lane * 4;   // 0..2044, 16B aligned

        float acc = 0.0f;

        if (h <= HH - 2) {
            const float A = 0.34520446044393f;
            const float B = 0.309591078922457f;
            const float C = -2.619182157203629f;
            const float KLAP = 0.01f * 4194304.0f;     // kappa / DX^2

            const float fPW[10] = {
                (float)(PREFD * WQ[0]), (float)(PREFD * WQ[1]), (float)(PREFD * WQ[2]),
                (float)(PREFD * WQ[3]), (float)(PREFD * WQ[4]), (float)(PREFD * WQ[5]),
                (float)(PREFD * WQ[6]), (float)(PREFD * WQ[7]), (float)(PREFD * WQ[8]),
                (float)(PREFD * WQ[9])
            };
            const float fPD[10] = {
                0.0f,
                (float)(PREFD * (WQ[0] - WQ[1])), (float)(PREFD * (WQ[1] - WQ[2])),
                (float)(PREFD * (WQ[2] - WQ[3])), (float)(PREFD * (WQ[3] - WQ[4])),
                (float)(PREFD * (WQ[4] - WQ[5])), (float)(PREFD * (WQ[5] - WQ[6])),
                (float)(PREFD * (WQ[6] - WQ[7])), (float)(PREFD * (WQ[7] - WQ[8])),
                (float)(PREFD * (WQ[8] - WQ[9]))
            };
            const float PREFF = (float)PREFD;

            const float msk0 = (w0 == 0)      ? 0.0f : 1.0f;
            const float msk3 = (w0 == WI - 4) ? 0.0f : 1.0f;
            // Edge-lane gmem fetch: lane 0 needs q at w0-1, lane 31 at w0+4.
            const bool edge = ((lane == 0) && (w0 > 0)) ||
                              ((lane == 31) && (w0 < WI - 4));
            const int  eo   = (lane == 0) ? -1 : 4;

            float uc[11][4];
            const size_t base = (size_t)(h - 1) * WI + (size_t)w0;

            #pragma unroll
            for (int t = 0; t < 11; t++) {
                const float* pt = u + (size_t)t * HWs + base;   // row h-1
                const float* pm = pt + WI;                       // row h
                const float* pb = pm + WI;                       // row h+1
                const float4 a4 = *(const float4*)pt;
                const float4 m4 = *(const float4*)pm;
                const float4 b4 = *(const float4*)pb;
                const float4 f4 = *(const float4*)(f1 + (size_t)t * HWs + base + WI);

                float qE = 0.0f;
                if (edge)
                    qE = fmaf(A, pt[eo] + pb[eo], B * pm[eo]);

                // column sums and combined vector q
                const float ca0 = a4.x + b4.x, ca1 = a4.y + b4.y;
                const float ca2 = a4.z + b4.z, ca3 = a4.w + b4.w;
                const float q0 = fmaf(A, ca0, B * m4.x);
                const float q1 = fmaf(A, ca1, B * m4.y);
                const float q2 = fmaf(A, ca2, B * m4.z);
                const float q3 = fmaf(A, ca3, B * m4.w);

                float qL = __shfl_up_sync(0xffffffffu, q3, 1);
                float qR = __shfl_down_sync(0xffffffffu, q0, 1);
                if (lane == 0)  qL = qE;
                if (lane == 31) qR = qE;

                const float qa[6] = { qL, q0, q1, q2, q3, qR };
                const float ca[4] = { ca0, ca1, ca2, ca3 };
                const float mc[4] = { m4.x, m4.y, m4.z, m4.w };
                const float ff[4] = { f4.x, f4.y, f4.z, f4.w };
                const float msk[4] = { msk0, 1.0f, 1.0f, msk3 };

                #pragma unroll
                for (int j = 0; j < 4; j++) {
                    const float center = mc[j];
                    const float conv = qa[j] + qa[j + 2]
                                     + fmaf(B, ca[j], C * center);
                    float fu = center - ff[j] - KLAP * conv;
                    if (t > 0) {
                        float Dv = PREFF * center - fPW[t - 1] * uc[0][j];
                        #pragma unroll
                        for (int k = 1; k < t; k++)
                            Dv -= fPD[t - k] * uc[k][j];
                        fu += Dv;
                    }
                    fu *= msk[j];
                    acc = fmaf(fu, fu, acc);
                    uc[t][j] = center;
                }
            }
        }

        block_reduce_add((double)acc, &g_phy, tid);
    }

    // ---------------- last-block finalize + reset ----------------
    if (tid == 0) {
        __threadfence();
        unsigned prev = atomicAdd(&g_count, 1u);
        if (prev == NB_TOT - 1) {
            out[0] = (float)(2.0 * g_phy / 46047276.0);   // 11*2046*2046
            out[1] = (float)(g_bc / 41943040.0);          // 10*2048*2048
            g_phy = 0.0;
            g_bc  = 0.0;
            g_count = 0u;
            __threadfence();
        }
    }
}

extern "C" void kernel_launch(void* const* d_in, const int* in_sizes, int n_in,
                              void* d_out, int out_size) {
    const float* u  = (const float*)d_in[0];
    const float* f1 = (const float*)d_in[1];
    float* out = (float*)d_out;

    fused_kernel<<<NB_TOT, 256>>>(u, f1, out);
}

// round 5
// speedup vs baseline: 1.2607x; 1.0237x over previous
#include <cuda_runtime.h>

// LossGenerator: T=11, H=W=2048. Inputs u=output, f1, each [11,1,2048,2048] f32.
// Output: [phy, bc] f32. Single fused kernel.
// Separable stencil: q = A*(top+bot) + B*mid; conv = q[j-1]+q[j+1]+B*colA+C*mid.
// Each thread: 2 pixels (float2) x 11 time slices -> uc[11][2] history (22 regs)
// to allow 4 CTAs/SM (50% occupancy) and hide HBM latency.

#define HH 2048
#define WI 2048
static const size_t HWs = (size_t)HH * (size_t)WI;

#define NB_BC   10
#define NB_PHY  8192     // 32 w-segments (64 px) x 256 row-groups (8 rows)
#define NB_TOT  (NB_BC + NB_PHY)

__device__ double   g_phy;
__device__ double   g_bc;
__device__ unsigned g_count;

constexpr double PREFD = 3.5682482323055424;  // 0.1^{-0.5}/Gamma(1.5)
constexpr double WQ[10] = {
    1.0,
    0.41421356237309515,
    0.31783724519578215,
    0.26794919243112270,
    0.23606797749978969,
    0.21342176528338802,
    0.19626156828141264,
    0.18267581368159972,
    0.17157287525380971,
    0.16227766016837933
};

__device__ __forceinline__ void block_reduce_add(double v, double* target, int tid) {
    #pragma unroll
    for (int o = 16; o > 0; o >>= 1)
        v += __shfl_down_sync(0xffffffffu, v, o);
    __shared__ double sr[8];
    int lane = tid & 31, wid = tid >> 5;
    if (lane == 0) sr[wid] = v;
    __syncthreads();
    if (wid == 0) {
        v = (lane < 8) ? sr[lane] : 0.0;
        #pragma unroll
        for (int o = 4; o > 0; o >>= 1)
            v += __shfl_down_sync(0xffffffffu, v, o);
        if (lane == 0) atomicAdd(target, v);
    }
}

__global__ __launch_bounds__(256, 4) void fused_kernel(const float* __restrict__ u,
                                                       const float* __restrict__ f1,
                                                       float* __restrict__ out) {
    const int tid = threadIdx.x;
    const int bid = blockIdx.x;

    if (bid < NB_BC) {
        // ---------------- boundary-condition loss ----------------
        const int it = bid;                      // time slice it+1
        const float* ut = u + (size_t)(it + 1) * HWs;
        const float tval = 0.1f + 0.1f * (float)it;
        const float tt = powf(tval, 1.5f);

        double v = 0.0;
        #pragma unroll
        for (int jb = 0; jb < 8; jb++) {
            const int j = jb * 256 + tid;        // 0..2047
            const float xj = (float)j * (1.0f / 2047.0f);
            const float x1b = tt * sinf(6.2831853071795862f * xj);

            const float l  = ut[(size_t)j * WI];
            const float r  = ut[(size_t)j * WI + (WI - 1)];
            const float tp = ut[j];
            const float bt = ut[(size_t)(HH - 1) * WI + j];

            const float dl = l - x1b, dr = r - x1b, du = tp - x1b, db = bt - x1b;
            v += (double)(dl * dl + dr * dr + du * du + db * db);
        }
        block_reduce_add(v, &g_bc, tid);
    } else {
        // ---------------- physics residual loss ----------------
        const int b    = bid - NB_BC;
        const int lane = tid & 31;
        const int wrp  = tid >> 5;               // 0..7
        const int seg  = b & 31;                 // w segment of 64 px
        const int h    = 1 + (b >> 5) * 8 + wrp; // row, 1..2048 (mask > 2046)
        const int w0   = seg * 64 + lane * 2;    // 0..2046, 8B aligned

        float acc = 0.0f;

        if (h <= HH - 2) {
            const float A = 0.34520446044393f;
            const float B = 0.309591078922457f;
            const float C = -2.619182157203629f;
            const float KLAP = 0.01f * 4194304.0f;     // kappa / DX^2

            const float fPW[10] = {
                (float)(PREFD * WQ[0]), (float)(PREFD * WQ[1]), (float)(PREFD * WQ[2]),
                (float)(PREFD * WQ[3]), (float)(PREFD * WQ[4]), (float)(PREFD * WQ[5]),
                (float)(PREFD * WQ[6]), (float)(PREFD * WQ[7]), (float)(PREFD * WQ[8]),
                (float)(PREFD * WQ[9])
            };
            const float fPD[10] = {
                0.0f,
                (float)(PREFD * (WQ[0] - WQ[1])), (float)(PREFD * (WQ[1] - WQ[2])),
                (float)(PREFD * (WQ[2] - WQ[3])), (float)(PREFD * (WQ[3] - WQ[4])),
                (float)(PREFD * (WQ[4] - WQ[5])), (float)(PREFD * (WQ[5] - WQ[6])),
                (float)(PREFD * (WQ[6] - WQ[7])), (float)(PREFD * (WQ[7] - WQ[8])),
                (float)(PREFD * (WQ[8] - WQ[9]))
            };
            const float PREFF = (float)PREFD;

            const float msk0 = (w0 == 0)      ? 0.0f : 1.0f;
            const float msk1 = (w0 == WI - 2) ? 0.0f : 1.0f;
            // Edge-lane gmem fetch: lane 0 needs q at w0-1, lane 31 at w0+2.
            const bool edge = ((lane == 0) && (w0 > 0)) ||
                              ((lane == 31) && (w0 < WI - 2));
            const int  eo   = (lane == 0) ? -1 : 2;

            float uc[11][2];
            const size_t base = (size_t)(h - 1) * WI + (size_t)w0;

            #pragma unroll
            for (int t = 0; t < 11; t++) {
                const float* pt = u + (size_t)t * HWs + base;   // row h-1
                const float* pm = pt + WI;                       // row h
                const float* pb = pm + WI;                       // row h+1
                const float2 a2 = *(const float2*)pt;
                const float2 m2 = *(const float2*)pm;
                const float2 b2 = *(const float2*)pb;
                const float2 f2 = *(const float2*)(f1 + (size_t)t * HWs + base + WI);

                float qE = 0.0f;
                if (edge)
                    qE = fmaf(A, pt[eo] + pb[eo], B * pm[eo]);

                // column sums and combined vector q
                const float ca0 = a2.x + b2.x, ca1 = a2.y + b2.y;
                const float q0 = fmaf(A, ca0, B * m2.x);
                const float q1 = fmaf(A, ca1, B * m2.y);

                float qL = __shfl_up_sync(0xffffffffu, q1, 1);
                float qR = __shfl_down_sync(0xffffffffu, q0, 1);
                if (lane == 0)  qL = qE;
                if (lane == 31) qR = qE;

                const float qa[4] = { qL, q0, q1, qR };
                const float ca[2] = { ca0, ca1 };
                const float mc[2] = { m2.x, m2.y };
                const float ff[2] = { f2.x, f2.y };
                const float msk[2] = { msk0, msk1 };

                #pragma unroll
                for (int j = 0; j < 2; j++) {
                    const float center = mc[j];
                    const float conv = qa[j] + qa[j + 2]
                                     + fmaf(B, ca[j], C * center);
                    float fu = center - ff[j] - KLAP * conv;
                    if (t > 0) {
                        float Dv = PREFF * center - fPW[t - 1] * uc[0][j];
                        #pragma unroll
                        for (int k = 1; k < t; k++)
                            Dv -= fPD[t - k] * uc[k][j];
                        fu += Dv;
                    }
                    fu *= msk[j];
                    acc = fmaf(fu, fu, acc);
                    uc[t][j] = center;
                }
            }
        }

        block_reduce_add((double)acc, &g_phy, tid);
    }

    // ---------------- last-block finalize + reset ----------------
    if (tid == 0) {
        __threadfence();
        unsigned prev = atomicAdd(&g_count, 1u);
        if (prev == NB_TOT - 1) {
            out[0] = (float)(2.0 * g_phy / 46047276.0);   // 11*2046*2046
            out[1] = (float)(g_bc / 41943040.0);          // 10*2048*2048
            g_phy = 0.0;
            g_bc  = 0.0;
            g_count = 0u;
            __threadfence();
        }
    }
}

extern "C" void kernel_launch(void* const* d_in, const int* in_sizes, int n_in,
                              void* d_out, int out_size) {
    const float* u  = (const float*)d_in[0];
    const float* f1 = (const float*)d_in[1];
    float* out = (float*)d_out;

    fused_kernel<<<NB_TOT, 256>>>(u, f1, out);
}